// round 14
// baseline (speedup 1.0000x reference)
#include <cuda_runtime.h>
#include <stdint.h>

// Problem constants
#define HH     450
#define HH2S   900
#define NM     6000
#define KN     6
#define NB     256
#define NDEPTH 15

#define SP    464          // padded row stride (29*16)
#define SP2   928          // padded 2H stride (58*16)
#define MPAD  6016         // padded message rows (47*128)
#define WNW   960          // wide-GEMM cols / hUz stride (15*64)
#define HZOFF 480          // col offset of Wz2 block in wide output
#define KC1   29           // K chunks for K=464
#define KC2   58           // K chunks for K=928

// permuted position of orig col k within its 16-block: p = 4*(k%4) + k/4
#define PPOS(k) ((((k) & 3) << 2) | (((k) >> 2) & 3))
__device__ __forceinline__ int pidx(int c) { return (c & ~15) | PPOS(c & 15); }

// ---------------- scratch (device globals) -----------------------------------
__device__ __align__(16) float g_x  [MPAD * SP];    // tf32-rounded, PERMUTED
__device__ __align__(16) float g_xz [MPAD * SP];    // natural
__device__ __align__(16) float g_xr [MPAD * SP];
__device__ __align__(16) float g_xh [MPAD * SP];
__device__ __align__(16) float g_hA [MPAD * SP];    // fp32 state, natural
__device__ __align__(16) float g_hB [MPAD * SP];
__device__ __align__(16) float g_hrA[MPAD * SP];    // tf32-rounded, PERMUTED
__device__ __align__(16) float g_hrB[MPAD * SP];
__device__ __align__(16) float g_hUz[MPAD * WNW];   // natural
__device__ __align__(16) float g_sh [MPAD * SP];
__device__ __align__(16) float g_zp [MPAD * SP];
__device__ __align__(16) float g_sgr[MPAD * SP];    // rounded, PERMUTED
__device__ __align__(16) float g_rootr[NB * SP2];   // rounded, PERMUTED
__device__ __align__(16) float g_d1r [NB * SP];     // rounded, PERMUTED
__device__ __align__(16) float g_d2  [NB * SP];     // natural
// pre-rounded, repacked, PERMUTED weights
__device__ __align__(16) float g_wz1[512 * SP];
__device__ __align__(16) float g_wr [512 * SP];
__device__ __align__(16) float g_wh1[512 * SP];
__device__ __align__(16) float g_wh2[512 * SP];
__device__ __align__(16) float g_d2w[512 * SP];
__device__ __align__(16) float g_wuz[WNW * SP];     // [Ur rows 0-449 | Wz2 rows 480-929]
__device__ __align__(16) float g_d1w[512 * SP2];

// ---------------- math helpers ------------------------------------------------
__device__ __forceinline__ float sigmoid_(float t) {
    return 1.0f / (1.0f + __expf(-t));
}
__device__ __forceinline__ float tanh_(float t) {
    t = fminf(fmaxf(t, -12.0f), 12.0f);
    float e = __expf(2.0f * t);
    return (e - 1.0f) / (e + 1.0f);
}
__device__ __forceinline__ uint32_t f2tf32(float f) {
    uint32_t r;
    asm("cvt.rna.tf32.f32 %0, %1;" : "=r"(r) : "f"(f));
    return r;
}
__device__ __forceinline__ float tf32r(float f) {
    return __uint_as_float(f2tf32(f));
}
__device__ __forceinline__ void mma8(float* c, uint32_t a0, uint32_t a1,
                                     uint32_t a2, uint32_t a3,
                                     uint32_t b0, uint32_t b1) {
    asm volatile(
        "mma.sync.aligned.m16n8k8.row.col.f32.tf32.tf32.f32 "
        "{%0,%1,%2,%3}, {%4,%5,%6,%7}, {%8,%9}, {%0,%1,%2,%3};"
        : "+f"(c[0]), "+f"(c[1]), "+f"(c[2]), "+f"(c[3])
        : "r"(a0), "r"(a1), "r"(a2), "r"(a3), "r"(b0), "r"(b1));
}
#define U(x) __float_as_uint(x)

// ---------------- direct-LDG tf32 GEMM (no shared memory) ----------------------
// A,B pre-rounded tf32 in PERMUTED k-layout: a thread's MMA fragment is a
// contiguous float4 IN GLOBAL MEMORY. Fragments load via LDG.128 straight from
// L1/L2 — no cp.async, no STS, no barriers, no stage bookkeeping. K-loop fully
// unrolled (KCH is a template param), so every load is [base + immediate].
// Tile 128x64, 256 thr, 8 warps (4x2 grid of 32x32 warp tiles), fp32 accum.
// EPI: 0 = +bias(opt) -> Cf ; 1 = +bias, leaky(0.1) -> Cf/Cr ; 2 = GRU gate.
template <int EPI, int KCH>
__global__ __launch_bounds__(256)
void gemm_d(const float* __restrict__ A, int lda,
            const float* __restrict__ Bw, int ldb,
            const float* __restrict__ bias,
            float* __restrict__ Cf, float* __restrict__ Cr, int ldc,
            const float* __restrict__ exz, const float* __restrict__ exh,
            const float* __restrict__ esh, const float* __restrict__ ezp)
{
    const int tid  = threadIdx.x;
    const int lane = tid & 31;
    const int w    = tid >> 5;
    const int bm = blockIdx.y * 128;
    const int bn = blockIdx.x * 64;
    const int wm = (w & 3) * 32;
    const int wn = (w >> 2) * 32;
    const int gr = lane >> 2;
    const int gc = lane & 3;

    // fragment base pointers (computed once; loop offsets are immediates)
    const float* pa0 = A + (size_t)(bm + wm + gr) * lda + gc * 4;
    const float* pa1 = pa0 + (size_t)8  * lda;
    const float* pa2 = pa0 + (size_t)16 * lda;
    const float* pa3 = pa0 + (size_t)24 * lda;
    const float* pb0 = Bw + (size_t)(bn + wn + gr) * ldb + gc * 4;
    const float* pb1 = pb0 + (size_t)8  * ldb;
    const float* pb2 = pb0 + (size_t)16 * ldb;
    const float* pb3 = pb0 + (size_t)24 * ldb;

    float acc[2][4][4] = {};

    #pragma unroll
    for (int kc = 0; kc < KCH; kc++) {
        const int ko = kc * 16;
        float4 av[2][2], bv[4];
        av[0][0] = *reinterpret_cast<const float4*>(pa0 + ko);
        av[0][1] = *reinterpret_cast<const float4*>(pa1 + ko);
        av[1][0] = *reinterpret_cast<const float4*>(pa2 + ko);
        av[1][1] = *reinterpret_cast<const float4*>(pa3 + ko);
        bv[0]    = *reinterpret_cast<const float4*>(pb0 + ko);
        bv[1]    = *reinterpret_cast<const float4*>(pb1 + ko);
        bv[2]    = *reinterpret_cast<const float4*>(pb2 + ko);
        bv[3]    = *reinterpret_cast<const float4*>(pb3 + ko);

        #pragma unroll
        for (int mt = 0; mt < 2; mt++)
            #pragma unroll
            for (int nt = 0; nt < 4; nt++)
                mma8(acc[mt][nt],
                     U(av[mt][0].x), U(av[mt][1].x), U(av[mt][0].y), U(av[mt][1].y),
                     U(bv[nt].x), U(bv[nt].y));
        #pragma unroll
        for (int mt = 0; mt < 2; mt++)
            #pragma unroll
            for (int nt = 0; nt < 4; nt++)
                mma8(acc[mt][nt],
                     U(av[mt][0].z), U(av[mt][1].z), U(av[mt][0].w), U(av[mt][1].w),
                     U(bv[nt].z), U(bv[nt].w));
    }

    // ---- epilogue (proven indexing, unchanged from R11)
    #pragma unroll
    for (int mt = 0; mt < 2; mt++) {
        #pragma unroll
        for (int half = 0; half < 2; half++) {
            int row = bm + wm + mt * 16 + gr + half * 8;
            #pragma unroll
            for (int nt = 0; nt < 4; nt++) {
                int col = bn + wn + nt * 8 + gc * 2;
                if (col >= ldc) continue;
                float v0 = acc[mt][nt][half * 2 + 0];
                float v1 = acc[mt][nt][half * 2 + 1];
                if (EPI == 0) {
                    if (bias && col < HH) { v0 += bias[col]; v1 += bias[col + 1]; }
                    *reinterpret_cast<float2*>(Cf + (size_t)row * ldc + col) =
                        make_float2(v0, v1);
                } else if (EPI == 1) {
                    if (bias && col < HH) { v0 += bias[col]; v1 += bias[col + 1]; }
                    v0 = (v0 > 0.0f) ? v0 : 0.1f * v0;
                    v1 = (v1 > 0.0f) ? v1 : 0.1f * v1;
                    if (Cf)
                        *reinterpret_cast<float2*>(Cf + (size_t)row * ldc + col) =
                            make_float2(v0, v1);
                    if (Cr) {
                        size_t rb = (size_t)row * ldc;
                        Cr[rb + pidx(col)]     = tf32r(v0);
                        Cr[rb + pidx(col + 1)] = tf32r(v1);
                    }
                } else {   // GRU gate: acc = sg@Wh2^T
                    float h0 = 0.0f, h1 = 0.0f;
                    if (row != 0) {
                        size_t o = (size_t)row * SP + col;
                        float2 xzv = *reinterpret_cast<const float2*>(exz + o);
                        float2 xhv = *reinterpret_cast<const float2*>(exh + o);
                        float2 shv = *reinterpret_cast<const float2*>(esh + o);
                        float2 zpv = *reinterpret_cast<const float2*>(ezp + o);
                        float z0 = sigmoid_(xzv.x + zpv.x);
                        float z1 = sigmoid_(xzv.y + zpv.y);
                        float p0 = tanh_(xhv.x + v0);
                        float p1 = tanh_(xhv.y + v1);
                        h0 = (1.0f - z0) * shv.x + z0 * p0;
                        h1 = (1.0f - z1) * shv.y + z1 * p1;
                    }
                    size_t rb = (size_t)row * SP;
                    *reinterpret_cast<float2*>(Cf + rb + col) = make_float2(h0, h1);
                    Cr[rb + pidx(col)]     = tf32r(h0);
                    Cr[rb + pidx(col + 1)] = tf32r(h1);
                }
            }
        }
    }
}

// ---------------- weight prep: round, repack, PERMUTE --------------------------
__global__ void prep_w(const float* __restrict__ Wz, const float* __restrict__ Wr,
                       const float* __restrict__ Ur, const float* __restrict__ Wh,
                       const float* __restrict__ D1, const float* __restrict__ D2,
                       float* __restrict__ wz1, float* __restrict__ wr,
                       float* __restrict__ wh1, float* __restrict__ wh2,
                       float* __restrict__ d2w, float* __restrict__ wuz,
                       float* __restrict__ d1w)
{
    int mat = blockIdx.y;
    int idx = blockIdx.x * 256 + threadIdx.x;
    if (mat < 5) {
        if (idx >= 512 * SP) return;
        int r = idx / SP, c = idx % SP;   // c = ORIGINAL column
        float v = 0.0f;
        if (r < HH && c < HH) {
            switch (mat) {
                case 0: v = Wz[r * HH2S + c];      break;
                case 1: v = Wr[r * HH + c];        break;
                case 2: v = Wh[r * HH2S + c];      break;
                case 3: v = Wh[r * HH2S + HH + c]; break;
                case 4: v = D2[r * HH + c];        break;
            }
            v = tf32r(v);
        }
        int o = r * SP + pidx(c);
        switch (mat) {
            case 0: wz1[o] = v; break;
            case 1: wr [o] = v; break;
            case 2: wh1[o] = v; break;
            case 3: wh2[o] = v; break;
            case 4: d2w[o] = v; break;
        }
    } else if (mat == 5) {   // wuz: [Ur @ rows 0-449 | Wz2 @ rows 480-929]
        if (idx >= WNW * SP) return;
        int r = idx / SP, c = idx % SP;
        float v = 0.0f;
        if (c < HH) {
            if (r < HH)                            v = tf32r(Ur[r * HH + c]);
            else if (r >= HZOFF && r - HZOFF < HH) v = tf32r(Wz[(r - HZOFF) * HH2S + HH + c]);
        }
        wuz[r * SP + pidx(c)] = v;
    } else {                 // d1w: 512 x SP2
        if (idx >= 512 * SP2) return;
        int r = idx / SP2, c = idx % SP2;
        float v = 0.0f;
        if (r < HH) {
            if (c < HH)                      v = tf32r(D1[r * HH2S + c]);
            else if (c >= SP && c - SP < HH) v = tf32r(D1[r * HH2S + HH + (c - SP)]);
        }
        d1w[r * SP2 + pidx(c)] = v;
    }
}

// ---------------- x = tf32(emb[fnode[fmess]]), permuted ------------------------
__global__ void x_gather(const float* __restrict__ emb,
                         const int* __restrict__ fnode,
                         const int* __restrict__ fmess,
                         float* __restrict__ x)
{
    int m = blockIdx.x;
    int e = (m < NM) ? fnode[fmess[m]] : 0;
    for (int c = threadIdx.x; c < SP; c += 256) {
        float v = 0.0f;
        if (m < NM && c < HH) v = tf32r(emb[(size_t)e * HH + c]);
        x[(size_t)m * SP + pidx(c)] = v;
    }
}

// ---------------- first GRU step (h0 = 0): h natural + rounded permuted --------
__global__ void init_h(const float* __restrict__ xz, const float* __restrict__ xh,
                       float* __restrict__ h, float* __restrict__ hr)
{
    int m = blockIdx.x;
    for (int c = threadIdx.x; c < SP; c += 256) {
        size_t o = (size_t)m * SP;
        float v = 0.0f;
        if (m > 0 && m < NM && c < HH)
            v = sigmoid_(xz[o + c]) * tanh_(xh[o + c]);
        h[o + c] = v;
        hr[o + pidx(c)] = tf32r(v);
    }
}

// ---------------- gather: sh, zp (natural), sg (rounded permuted) --------------
__global__ void gather_k(const float* __restrict__ h, const float* __restrict__ hUz,
                         const float* __restrict__ xr, const int* __restrict__ mg,
                         float* __restrict__ sh, float* __restrict__ zp,
                         float* __restrict__ sgr)
{
    int m = blockIdx.x;
    int j = threadIdx.x * 4;
    if (j >= SP) return;
    size_t o = (size_t)m * SP + j;
    size_t pb = (size_t)m * SP + (j & ~15);
    int q = (j & 15) >> 2;   // quad index within 16-block
    if (m >= NM) {
        *reinterpret_cast<float4*>(sh + o) = make_float4(0.f, 0.f, 0.f, 0.f);
        *reinterpret_cast<float4*>(zp + o) = make_float4(0.f, 0.f, 0.f, 0.f);
        sgr[pb + q] = 0.f; sgr[pb + 4 + q] = 0.f;
        sgr[pb + 8 + q] = 0.f; sgr[pb + 12 + q] = 0.f;
        return;
    }
    float4 xr4 = *reinterpret_cast<const float4*>(xr + o);
    float4 s4 = make_float4(0.f, 0.f, 0.f, 0.f);
    float4 z4 = make_float4(0.f, 0.f, 0.f, 0.f);
    float4 g4 = make_float4(0.f, 0.f, 0.f, 0.f);
    #pragma unroll
    for (int k = 0; k < KN; k++) {
        int idx = mg[m * KN + k];
        size_t qx = (size_t)idx * WNW + j;
        float4 h4  = *reinterpret_cast<const float4*>(h + (size_t)idx * SP + j);
        float4 hu4 = *reinterpret_cast<const float4*>(hUz + qx);
        float4 hz4 = *reinterpret_cast<const float4*>(hUz + qx + HZOFF);
        s4.x += h4.x; s4.y += h4.y; s4.z += h4.z; s4.w += h4.w;
        z4.x += hz4.x; z4.y += hz4.y; z4.z += hz4.z; z4.w += hz4.w;
        g4.x += sigmoid_(xr4.x + hu4.x) * h4.x;
        g4.y += sigmoid_(xr4.y + hu4.y) * h4.y;
        g4.z += sigmoid_(xr4.z + hu4.z) * h4.z;
        g4.w += sigmoid_(xr4.w + hu4.w) * h4.w;
    }
    *reinterpret_cast<float4*>(sh + o) = s4;
    *reinterpret_cast<float4*>(zp + o) = z4;
    // permuted scatter: orig col j+e -> position 4e + q within the block
    sgr[pb + q]      = tf32r(g4.x);
    sgr[pb + 4 + q]  = tf32r(g4.y);
    sgr[pb + 8 + q]  = tf32r(g4.z);
    sgr[pb + 12 + q] = tf32r(g4.w);
}

// ---------------- root vectors (rounded, permuted), stride 928 -----------------
__global__ void root_k(const float* __restrict__ emb, const int* __restrict__ fnode,
                       const int* __restrict__ ridx, const int* __restrict__ ng,
                       const float* __restrict__ h, float* __restrict__ rootr)
{
    int b = blockIdx.x;
    int node = ridx[b];
    int e = fnode[node];
    for (int j = threadIdx.x; j < SP2; j += blockDim.x) {
        float v = 0.0f;
        if (j < HH) {
            v = emb[(size_t)e * HH + j];
        } else if (j >= SP && j - SP < HH) {
            int c = j - SP;
            float s = 0.0f;
            #pragma unroll
            for (int k = 0; k < KN; k++) {
                int mi = ng[node * KN + k];
                s += h[(size_t)mi * SP + c];
            }
            v = s;
        }
        rootr[(size_t)b * SP2 + pidx(j)] = tf32r(v);
    }
}

// ---------------- final D3 dot product -----------------------------------------
__global__ void d3_k(const float* __restrict__ d2, const float* __restrict__ w,
                     const float* __restrict__ bb, float* __restrict__ out)
{
    int b = blockIdx.x;
    float s = 0.0f;
    for (int i = threadIdx.x; i < HH; i += blockDim.x)
        s += d2[(size_t)b * SP + i] * w[i];
    __shared__ float red[128];
    red[threadIdx.x] = s;
    __syncthreads();
    for (int st = 64; st > 0; st >>= 1) {
        if (threadIdx.x < st) red[threadIdx.x] += red[threadIdx.x + st];
        __syncthreads();
    }
    if (threadIdx.x == 0) out[b] = red[0] + bb[0];
}

// ---------------- launch ---------------------------------------------------------
extern "C" void kernel_launch(void* const* d_in, const int* in_sizes, int n_in,
                              void* d_out, int out_size)
{
    const int*   fnode      = (const int*)d_in[0];
    const int*   fmess      = (const int*)d_in[1];
    const int*   node_graph = (const int*)d_in[2];
    const int*   mess_graph = (const int*)d_in[3];
    const int*   root_idx   = (const int*)d_in[4];
    const float* emb        = (const float*)d_in[5];
    const float* Wz         = (const float*)d_in[6];
    const float* Wz_b       = (const float*)d_in[7];
    const float* Wr         = (const float*)d_in[8];
    const float* Ur         = (const float*)d_in[9];
    const float* Ur_b       = (const float*)d_in[10];
    const float* Wh         = (const float*)d_in[11];
    const float* Wh_b       = (const float*)d_in[12];
    const float* D1w        = (const float*)d_in[13];
    const float* D1b        = (const float*)d_in[14];
    const float* D2w        = (const float*)d_in[15];
    const float* D2b        = (const float*)d_in[16];
    const float* D3w        = (const float*)d_in[17];
    const float* D3b        = (const float*)d_in[18];
    float* out = (float*)d_out;

    float *x, *xz, *xr, *xh, *hA, *hB, *hrA, *hrB, *hUz, *sh, *zp, *sgr;
    float *rootr, *d1r, *d2;
    float *wz1, *wr, *wh1, *wh2, *d2w, *wuz, *d1w;
    cudaGetSymbolAddress((void**)&x,     g_x);
    cudaGetSymbolAddress((void**)&xz,    g_xz);
    cudaGetSymbolAddress((void**)&xr,    g_xr);
    cudaGetSymbolAddress((void**)&xh,    g_xh);
    cudaGetSymbolAddress((void**)&hA,    g_hA);
    cudaGetSymbolAddress((void**)&hB,    g_hB);
    cudaGetSymbolAddress((void**)&hrA,   g_hrA);
    cudaGetSymbolAddress((void**)&hrB,   g_hrB);
    cudaGetSymbolAddress((void**)&hUz,   g_hUz);
    cudaGetSymbolAddress((void**)&sh,    g_sh);
    cudaGetSymbolAddress((void**)&zp,    g_zp);
    cudaGetSymbolAddress((void**)&sgr,   g_sgr);
    cudaGetSymbolAddress((void**)&rootr, g_rootr);
    cudaGetSymbolAddress((void**)&d1r,   g_d1r);
    cudaGetSymbolAddress((void**)&d2,    g_d2);
    cudaGetSymbolAddress((void**)&wz1,   g_wz1);
    cudaGetSymbolAddress((void**)&wr,    g_wr);
    cudaGetSymbolAddress((void**)&wh1,   g_wh1);
    cudaGetSymbolAddress((void**)&wh2,   g_wh2);
    cudaGetSymbolAddress((void**)&d2w,   g_d2w);
    cudaGetSymbolAddress((void**)&wuz,   g_wuz);
    cudaGetSymbolAddress((void**)&d1w,   g_d1w);

    // weight prep (round + repack + permute)
    dim3 pgrid((512 * SP2 + 255) / 256, 7);
    prep_w<<<pgrid, 256>>>(Wz, Wr, Ur, Wh, D1w, D2w,
                           wz1, wr, wh1, wh2, d2w, wuz, d1w);

    // x = tf32(emb[fnode[fmess]]) permuted
    x_gather<<<MPAD, 256>>>(emb, fnode, fmess, x);

    dim3 blk(256);
    dim3 gx(8, MPAD / 128);    // N=464 GEMMs (8 x 47)
    dim3 gw(15, MPAD / 128);   // wide GEMM, N=960 (15 x 47)

    // Loop-invariant x-projections (biases folded in)
    gemm_d<0, KC1><<<gx, blk>>>(x, SP, wz1, SP, Wz_b, xz, nullptr, SP, 0, 0, 0, 0);
    gemm_d<0, KC1><<<gx, blk>>>(x, SP, wr,  SP, Ur_b, xr, nullptr, SP, 0, 0, 0, 0);
    gemm_d<0, KC1><<<gx, blk>>>(x, SP, wh1, SP, Wh_b, xh, nullptr, SP, 0, 0, 0, 0);

    // Step 1 specialized for h0 = 0
    init_h<<<MPAD, 256>>>(xz, xh, hA, hrA);

    float* hcur = hA;   float* hcurR = hrA;
    float* hnxt = hB;   float* hnxtR = hrB;
    for (int it = 0; it < NDEPTH - 1; ++it) {
        // wide: [hU | hz] = h @ [Ur | Wz2]^T  (N = 960)
        gemm_d<0, KC1><<<gw, blk>>>(hcurR, SP, wuz, SP, nullptr, hUz, nullptr,
                                    WNW, 0, 0, 0, 0);
        // sh, zp, sg in one pass
        gather_k<<<MPAD, 128>>>(hcur, hUz, xr, mess_graph, sh, zp, sgr);
        // h_new = GRU(sg @ Wh2^T) fused epilogue -> h natural + rounded permuted
        gemm_d<2, KC1><<<gx, blk>>>(sgr, SP, wh2, SP, nullptr, hnxt, hnxtR,
                                    SP, xz, xh, sh, zp);
        float* t = hcur; hcur = hnxt; hnxt = t;
        float* tr = hcurR; hcurR = hnxtR; hnxtR = tr;
    }

    // Root vectors + discriminator MLP
    root_k<<<NB, 256>>>(emb, fnode, root_idx, node_graph, hcur, rootr);

    dim3 gd(8, NB / 128);   // (8, 2)
    gemm_d<1, KC2><<<gd, blk>>>(rootr, SP2, d1w, SP2, D1b, nullptr, d1r,
                                SP, 0, 0, 0, 0);
    gemm_d<1, KC1><<<gd, blk>>>(d1r, SP, d2w, SP, D2b, d2, nullptr,
                                SP, 0, 0, 0, 0);
    d3_k<<<NB, 128>>>(d2, D3w, D3b, out);
}

// round 15
// speedup vs baseline: 1.2542x; 1.2542x over previous
#include <cuda_runtime.h>
#include <stdint.h>

// Problem constants
#define HH     450
#define HH2S   900
#define NM     6000
#define KN     6
#define NB     256
#define NDEPTH 15

#define SP    464          // padded row stride (29*16)
#define SP2   928          // padded 2H stride (58*16)
#define MPAD  6016         // padded message rows (47*128)
#define WNW   960          // wide-GEMM cols / hUz stride (15*64)
#define HZOFF 480          // col offset of Wz2 block in wide output
#define XPN   1408         // packed x-proj B rows (22*64); real 1392 = 3*464

// permuted position of orig col k within its 16-block: p = 4*(k%4) + k/4
#define PPOS(k) ((((k) & 3) << 2) | (((k) >> 2) & 3))
__device__ __forceinline__ int pidx(int c) { return (c & ~15) | PPOS(c & 15); }

// ---------------- scratch (device globals) -----------------------------------
__device__ __align__(16) float g_x  [MPAD * SP];    // tf32-rounded, PERMUTED
__device__ __align__(16) float g_xz [MPAD * SP];    // natural
__device__ __align__(16) float g_xr [MPAD * SP];
__device__ __align__(16) float g_xh [MPAD * SP];
__device__ __align__(16) float g_hA [MPAD * SP];    // fp32 state, natural
__device__ __align__(16) float g_hB [MPAD * SP];
__device__ __align__(16) float g_hrA[MPAD * SP];    // tf32-rounded, PERMUTED
__device__ __align__(16) float g_hrB[MPAD * SP];
__device__ __align__(16) float g_hUz[MPAD * WNW];   // natural
__device__ __align__(16) float g_sh [MPAD * SP];
__device__ __align__(16) float g_zp [MPAD * SP];
__device__ __align__(16) float g_sgr[MPAD * SP];    // rounded, PERMUTED
__device__ __align__(16) float g_rootr[NB * SP2];   // rounded, PERMUTED
__device__ __align__(16) float g_d1r [NB * SP];     // rounded, PERMUTED
__device__ __align__(16) float g_d2  [NB * SP];     // natural
// pre-rounded, repacked, PERMUTED weights
__device__ __align__(16) float g_wxp[XPN * SP];     // [Wz1 | Wr | Wh1] packed
__device__ __align__(16) float g_wh2[512 * SP];
__device__ __align__(16) float g_d2w[512 * SP];
__device__ __align__(16) float g_wuz[WNW * SP];     // [Ur rows 0-449 | Wz2 rows 480-929]
__device__ __align__(16) float g_d1w[512 * SP2];

// ---------------- math helpers ------------------------------------------------
__device__ __forceinline__ float sigmoid_(float t) {
    return 1.0f / (1.0f + __expf(-t));
}
__device__ __forceinline__ float tanh_(float t) {
    t = fminf(fmaxf(t, -12.0f), 12.0f);
    float e = __expf(2.0f * t);
    return (e - 1.0f) / (e + 1.0f);
}
__device__ __forceinline__ uint32_t f2tf32(float f) {
    uint32_t r;
    asm("cvt.rna.tf32.f32 %0, %1;" : "=r"(r) : "f"(f));
    return r;
}
__device__ __forceinline__ float tf32r(float f) {
    return __uint_as_float(f2tf32(f));
}
__device__ __forceinline__ uint32_t smem_u32(const void* p) {
    uint32_t a;
    asm("{ .reg .u64 t; cvta.to.shared.u64 t, %1; cvt.u32.u64 %0, t; }"
        : "=r"(a) : "l"(p));
    return a;
}
__device__ __forceinline__ void cpa16(uint32_t dst, const void* src) {
    asm volatile("cp.async.cg.shared.global [%0], [%1], 16;\n" :: "r"(dst), "l"(src));
}
__device__ __forceinline__ void mma8(float* c, uint32_t a0, uint32_t a1,
                                     uint32_t a2, uint32_t a3,
                                     uint32_t b0, uint32_t b1) {
    asm volatile(
        "mma.sync.aligned.m16n8k8.row.col.f32.tf32.tf32.f32 "
        "{%0,%1,%2,%3}, {%4,%5,%6,%7}, {%8,%9}, {%0,%1,%2,%3};"
        : "+f"(c[0]), "+f"(c[1]), "+f"(c[2]), "+f"(c[3])
        : "r"(a0), "r"(a1), "r"(a2), "r"(a3), "r"(b0), "r"(b1));
}
#define U(x) __float_as_uint(x)

// ---------------- tf32 GEMM (R11-proven): permuted layout, static stages -------
// A,B pre-rounded tf32 in PERMUTED k-layout. C = A @ B^T, fp32 accum.
// Tile 128x64, 256 thr, warp 32x32, TBK=16, smem stride 16 (conflict-free).
// 3-stage cp.async pipeline, literal stage indices, pointer-increment addressing.
// EPI: 0 = +bias(opt) ; 1 = +bias, leaky(0.1) -> Cf/Cr ; 2 = GRU gate -> Cf+Cr ;
//      3 = x-proj routing: col region -> {Cf=xz, Cr=xr, C3=xh} with region bias.
#define TBM 128
#define TBN 64
#define TBK 16
#define ASTG (TBM * TBK)    // 2048 floats
#define BSTG (TBN * TBK)    // 1024 floats
#define STGF (ASTG + BSTG)  // 3072 floats / stage
#define STGB (STGF * 4)
#define SMEM_G (3 * STGB)   // 36864 bytes

#define ISSUE_LOAD(S_)                                                          \
    do {                                                                        \
        cpa16(dA0 + (S_) * STGB, pA0);                                          \
        cpa16(dA1 + (S_) * STGB, pA1);                                          \
        cpa16(dB  + (S_) * STGB, pB);                                           \
        pA0 += TBK; pA1 += TBK; pB += TBK;                                      \
    } while (0)

#define COMPUTE(S_)                                                             \
    do {                                                                        \
        const float* AS_ = dsm + (S_) * STGF;                                   \
        const float* BS_ = AS_ + ASTG;                                          \
        float4 av[2][2], bv[4];                                                 \
        _Pragma("unroll")                                                       \
        for (int mt = 0; mt < 2; mt++) {                                        \
            av[mt][0] = *reinterpret_cast<const float4*>(AS_ + aof0 + mt * (16 * TBK)); \
            av[mt][1] = *reinterpret_cast<const float4*>(AS_ + aof1 + mt * (16 * TBK)); \
        }                                                                       \
        _Pragma("unroll")                                                       \
        for (int nt = 0; nt < 4; nt++)                                          \
            bv[nt] = *reinterpret_cast<const float4*>(BS_ + bof + nt * (8 * TBK));      \
        _Pragma("unroll")                                                       \
        for (int mt = 0; mt < 2; mt++)                                          \
            _Pragma("unroll")                                                   \
            for (int nt = 0; nt < 4; nt++)                                      \
                mma8(acc[mt][nt],                                               \
                     U(av[mt][0].x), U(av[mt][1].x), U(av[mt][0].y), U(av[mt][1].y), \
                     U(bv[nt].x), U(bv[nt].y));                                 \
        _Pragma("unroll")                                                       \
        for (int mt = 0; mt < 2; mt++)                                          \
            _Pragma("unroll")                                                   \
            for (int nt = 0; nt < 4; nt++)                                      \
                mma8(acc[mt][nt],                                               \
                     U(av[mt][0].z), U(av[mt][1].z), U(av[mt][0].w), U(av[mt][1].w), \
                     U(bv[nt].z), U(bv[nt].w));                                 \
    } while (0)

#define STEP(kc_, CS_, LS_)                                                     \
    do {                                                                        \
        asm volatile("cp.async.wait_group 1;\n");                               \
        __syncthreads();                                                        \
        if ((kc_) + 2 < KCH) ISSUE_LOAD(LS_);                                   \
        asm volatile("cp.async.commit_group;\n");                               \
        COMPUTE(CS_);                                                           \
    } while (0)

template <int EPI>
__global__ __launch_bounds__(256, 3)
void gemm_p(const float* __restrict__ A, int lda,
            const float* __restrict__ Bw, int ldb,
            const float* __restrict__ bias,
            float* __restrict__ Cf, float* __restrict__ Cr,
            float* __restrict__ C3,
            int ldc, int KCH,
            const float* __restrict__ exz, const float* __restrict__ exh,
            const float* __restrict__ esh, const float* __restrict__ ezp)
{
    extern __shared__ __align__(16) float dsm[];
    const uint32_t sbase = smem_u32(dsm);

    const int tid  = threadIdx.x;
    const int lane = tid & 31;
    const int w    = tid >> 5;
    const int bm = blockIdx.y * TBM;
    const int bn = blockIdx.x * TBN;
    const int wm = (w & 3) * 32;
    const int wn = (w >> 2) * 32;
    const int gr = lane >> 2;
    const int gc = lane & 3;

    // loop-invariant addressing
    const int ldr  = tid >> 2;           // 0..63
    const int ldc4 = (tid & 3) * 4;      // 0,4,8,12
    const float* pA0 = A + (size_t)(bm + ldr) * lda + ldc4;
    const float* pA1 = pA0 + (size_t)64 * lda;
    const float* pB  = Bw + (size_t)(bn + ldr) * ldb + ldc4;
    const uint32_t dA0 = sbase + ((ldr * TBK + ldc4) << 2);
    const uint32_t dA1 = dA0 + ((64 * TBK) << 2);
    const uint32_t dB  = sbase + (((ASTG) + ldr * TBK + ldc4) << 2);
    // fragment offsets (floats)
    const int aof0 = (wm + gr) * TBK + gc * 4;
    const int aof1 = (wm + 8 + gr) * TBK + gc * 4;
    const int bof  = (wn + gr) * TBK + gc * 4;

    float acc[2][4][4] = {};

    ISSUE_LOAD(0);
    asm volatile("cp.async.commit_group;\n");
    ISSUE_LOAD(1);
    asm volatile("cp.async.commit_group;\n");

    int kc = 0;
    for (; kc + 2 < KCH; kc += 3) {
        STEP(kc,     0, 2);
        STEP(kc + 1, 1, 0);
        STEP(kc + 2, 2, 1);
    }
    if (kc < KCH)     STEP(kc,     0, 2);
    if (kc + 1 < KCH) STEP(kc + 1, 1, 0);

    // ---- epilogue (R11-proven indexing)
    #pragma unroll
    for (int mt = 0; mt < 2; mt++) {
        #pragma unroll
        for (int half = 0; half < 2; half++) {
            int row = bm + wm + mt * 16 + gr + half * 8;
            #pragma unroll
            for (int nt = 0; nt < 4; nt++) {
                int col = bn + wn + nt * 8 + gc * 2;
                float v0 = acc[mt][nt][half * 2 + 0];
                float v1 = acc[mt][nt][half * 2 + 1];
                if (EPI == 3) {
                    // route by column region: [0,464)=xz, [464,928)=xr, [928,1392)=xh
                    if (col >= 3 * SP) continue;
                    int which = (col >= 2 * SP) ? 2 : (col >= SP ? 1 : 0);
                    int cin = col - which * SP;
                    const float* bb = (which == 0) ? bias : (which == 1) ? exz : exh;
                    if (cin < HH) { v0 += bb[cin]; v1 += bb[cin + 1]; }
                    float* dst = (which == 0) ? Cf : (which == 1) ? Cr : C3;
                    *reinterpret_cast<float2*>(dst + (size_t)row * SP + cin) =
                        make_float2(v0, v1);
                    continue;
                }
                if (col >= ldc) continue;
                if (EPI == 0) {
                    if (bias && col < HH) { v0 += bias[col]; v1 += bias[col + 1]; }
                    *reinterpret_cast<float2*>(Cf + (size_t)row * ldc + col) =
                        make_float2(v0, v1);
                } else if (EPI == 1) {
                    if (bias && col < HH) { v0 += bias[col]; v1 += bias[col + 1]; }
                    v0 = (v0 > 0.0f) ? v0 : 0.1f * v0;
                    v1 = (v1 > 0.0f) ? v1 : 0.1f * v1;
                    if (Cf)
                        *reinterpret_cast<float2*>(Cf + (size_t)row * ldc + col) =
                            make_float2(v0, v1);
                    if (Cr) {
                        size_t rb = (size_t)row * ldc;
                        Cr[rb + pidx(col)]     = tf32r(v0);
                        Cr[rb + pidx(col + 1)] = tf32r(v1);
                    }
                } else {   // EPI == 2, GRU gate: acc = sg@Wh2^T
                    float h0 = 0.0f, h1 = 0.0f;
                    if (row != 0) {
                        size_t o = (size_t)row * SP + col;
                        float2 xzv = *reinterpret_cast<const float2*>(exz + o);
                        float2 xhv = *reinterpret_cast<const float2*>(exh + o);
                        float2 shv = *reinterpret_cast<const float2*>(esh + o);
                        float2 zpv = *reinterpret_cast<const float2*>(ezp + o);
                        float z0 = sigmoid_(xzv.x + zpv.x);
                        float z1 = sigmoid_(xzv.y + zpv.y);
                        float p0 = tanh_(xhv.x + v0);
                        float p1 = tanh_(xhv.y + v1);
                        h0 = (1.0f - z0) * shv.x + z0 * p0;
                        h1 = (1.0f - z1) * shv.y + z1 * p1;
                    }
                    size_t rb = (size_t)row * SP;
                    *reinterpret_cast<float2*>(Cf + rb + col) = make_float2(h0, h1);
                    Cr[rb + pidx(col)]     = tf32r(h0);
                    Cr[rb + pidx(col + 1)] = tf32r(h1);
                }
            }
        }
    }
}

// ---------------- weight prep: round, repack, PERMUTE --------------------------
__global__ void prep_w(const float* __restrict__ Wz, const float* __restrict__ Wr,
                       const float* __restrict__ Ur, const float* __restrict__ Wh,
                       const float* __restrict__ D1, const float* __restrict__ D2,
                       float* __restrict__ wxp, float* __restrict__ wh2,
                       float* __restrict__ d2w, float* __restrict__ wuz,
                       float* __restrict__ d1w)
{
    int mat = blockIdx.y;
    int idx = blockIdx.x * 256 + threadIdx.x;
    if (mat == 0) {          // wxp: rows [Wz1 | Wr | Wh1] at 0/464/928
        if (idx >= XPN * SP) return;
        int r = idx / SP, c = idx % SP;
        float v = 0.0f;
        if (c < HH) {
            if (r < HH)                           v = Wz[r * HH2S + c];
            else if (r >= SP && r - SP < HH)      v = Wr[(r - SP) * HH + c];
            else if (r >= 2 * SP && r - 2 * SP < HH) v = Wh[(r - 2 * SP) * HH2S + c];
            v = tf32r(v);
        }
        wxp[r * SP + pidx(c)] = v;
    } else if (mat == 1) {   // wh2
        if (idx >= 512 * SP) return;
        int r = idx / SP, c = idx % SP;
        float v = 0.0f;
        if (r < HH && c < HH) v = tf32r(Wh[r * HH2S + HH + c]);
        wh2[r * SP + pidx(c)] = v;
    } else if (mat == 2) {   // d2w
        if (idx >= 512 * SP) return;
        int r = idx / SP, c = idx % SP;
        float v = 0.0f;
        if (r < HH && c < HH) v = tf32r(D2[r * HH + c]);
        d2w[r * SP + pidx(c)] = v;
    } else if (mat == 3) {   // wuz: [Ur @ rows 0-449 | Wz2 @ rows 480-929]
        if (idx >= WNW * SP) return;
        int r = idx / SP, c = idx % SP;
        float v = 0.0f;
        if (c < HH) {
            if (r < HH)                            v = tf32r(Ur[r * HH + c]);
            else if (r >= HZOFF && r - HZOFF < HH) v = tf32r(Wz[(r - HZOFF) * HH2S + HH + c]);
        }
        wuz[r * SP + pidx(c)] = v;
    } else {                 // d1w: 512 x SP2
        if (idx >= 512 * SP2) return;
        int r = idx / SP2, c = idx % SP2;
        float v = 0.0f;
        if (r < HH) {
            if (c < HH)                      v = tf32r(D1[r * HH2S + c]);
            else if (c >= SP && c - SP < HH) v = tf32r(D1[r * HH2S + HH + (c - SP)]);
        }
        d1w[r * SP2 + pidx(c)] = v;
    }
}

// ---------------- x = tf32(emb[fnode[fmess]]), permuted ------------------------
__global__ void x_gather(const float* __restrict__ emb,
                         const int* __restrict__ fnode,
                         const int* __restrict__ fmess,
                         float* __restrict__ x)
{
    int m = blockIdx.x;
    int e = (m < NM) ? fnode[fmess[m]] : 0;
    for (int c = threadIdx.x; c < SP; c += 256) {
        float v = 0.0f;
        if (m < NM && c < HH) v = tf32r(emb[(size_t)e * HH + c]);
        x[(size_t)m * SP + pidx(c)] = v;
    }
}

// ---------------- first GRU step (h0 = 0): h natural + rounded permuted --------
__global__ void init_h(const float* __restrict__ xz, const float* __restrict__ xh,
                       float* __restrict__ h, float* __restrict__ hr)
{
    int m = blockIdx.x;
    for (int c = threadIdx.x; c < SP; c += 256) {
        size_t o = (size_t)m * SP;
        float v = 0.0f;
        if (m > 0 && m < NM && c < HH)
            v = sigmoid_(xz[o + c]) * tanh_(xh[o + c]);
        h[o + c] = v;
        hr[o + pidx(c)] = tf32r(v);
    }
}

// ---------------- gather: sh, zp (natural), sg (rounded permuted) --------------
__global__ void gather_k(const float* __restrict__ h, const float* __restrict__ hUz,
                         const float* __restrict__ xr, const int* __restrict__ mg,
                         float* __restrict__ sh, float* __restrict__ zp,
                         float* __restrict__ sgr)
{
    int m = blockIdx.x;
    int j = threadIdx.x * 4;
    if (j >= SP) return;
    size_t o = (size_t)m * SP + j;
    size_t pb = (size_t)m * SP + (j & ~15);
    int q = (j & 15) >> 2;   // quad index within 16-block
    if (m >= NM) {
        *reinterpret_cast<float4*>(sh + o) = make_float4(0.f, 0.f, 0.f, 0.f);
        *reinterpret_cast<float4*>(zp + o) = make_float4(0.f, 0.f, 0.f, 0.f);
        sgr[pb + q] = 0.f; sgr[pb + 4 + q] = 0.f;
        sgr[pb + 8 + q] = 0.f; sgr[pb + 12 + q] = 0.f;
        return;
    }
    float4 xr4 = *reinterpret_cast<const float4*>(xr + o);
    float4 s4 = make_float4(0.f, 0.f, 0.f, 0.f);
    float4 z4 = make_float4(0.f, 0.f, 0.f, 0.f);
    float4 g4 = make_float4(0.f, 0.f, 0.f, 0.f);
    #pragma unroll
    for (int k = 0; k < KN; k++) {
        int idx = mg[m * KN + k];
        size_t qx = (size_t)idx * WNW + j;
        float4 h4  = *reinterpret_cast<const float4*>(h + (size_t)idx * SP + j);
        float4 hu4 = *reinterpret_cast<const float4*>(hUz + qx);
        float4 hz4 = *reinterpret_cast<const float4*>(hUz + qx + HZOFF);
        s4.x += h4.x; s4.y += h4.y; s4.z += h4.z; s4.w += h4.w;
        z4.x += hz4.x; z4.y += hz4.y; z4.z += hz4.z; z4.w += hz4.w;
        g4.x += sigmoid_(xr4.x + hu4.x) * h4.x;
        g4.y += sigmoid_(xr4.y + hu4.y) * h4.y;
        g4.z += sigmoid_(xr4.z + hu4.z) * h4.z;
        g4.w += sigmoid_(xr4.w + hu4.w) * h4.w;
    }
    *reinterpret_cast<float4*>(sh + o) = s4;
    *reinterpret_cast<float4*>(zp + o) = z4;
    sgr[pb + q]      = tf32r(g4.x);
    sgr[pb + 4 + q]  = tf32r(g4.y);
    sgr[pb + 8 + q]  = tf32r(g4.z);
    sgr[pb + 12 + q] = tf32r(g4.w);
}

// ---------------- root vectors (rounded, permuted), stride 928 -----------------
__global__ void root_k(const float* __restrict__ emb, const int* __restrict__ fnode,
                       const int* __restrict__ ridx, const int* __restrict__ ng,
                       const float* __restrict__ h, float* __restrict__ rootr)
{
    int b = blockIdx.x;
    int node = ridx[b];
    int e = fnode[node];
    for (int j = threadIdx.x; j < SP2; j += blockDim.x) {
        float v = 0.0f;
        if (j < HH) {
            v = emb[(size_t)e * HH + j];
        } else if (j >= SP && j - SP < HH) {
            int c = j - SP;
            float s = 0.0f;
            #pragma unroll
            for (int k = 0; k < KN; k++) {
                int mi = ng[node * KN + k];
                s += h[(size_t)mi * SP + c];
            }
            v = s;
        }
        rootr[(size_t)b * SP2 + pidx(j)] = tf32r(v);
    }
}

// ---------------- final D3 dot product -----------------------------------------
__global__ void d3_k(const float* __restrict__ d2, const float* __restrict__ w,
                     const float* __restrict__ bb, float* __restrict__ out)
{
    int b = blockIdx.x;
    float s = 0.0f;
    for (int i = threadIdx.x; i < HH; i += blockDim.x)
        s += d2[(size_t)b * SP + i] * w[i];
    __shared__ float red[128];
    red[threadIdx.x] = s;
    __syncthreads();
    for (int st = 64; st > 0; st >>= 1) {
        if (threadIdx.x < st) red[threadIdx.x] += red[threadIdx.x + st];
        __syncthreads();
    }
    if (threadIdx.x == 0) out[b] = red[0] + bb[0];
}

// ---------------- launch ---------------------------------------------------------
extern "C" void kernel_launch(void* const* d_in, const int* in_sizes, int n_in,
                              void* d_out, int out_size)
{
    const int*   fnode      = (const int*)d_in[0];
    const int*   fmess      = (const int*)d_in[1];
    const int*   node_graph = (const int*)d_in[2];
    const int*   mess_graph = (const int*)d_in[3];
    const int*   root_idx   = (const int*)d_in[4];
    const float* emb        = (const float*)d_in[5];
    const float* Wz         = (const float*)d_in[6];
    const float* Wz_b       = (const float*)d_in[7];
    const float* Wr         = (const float*)d_in[8];
    const float* Ur         = (const float*)d_in[9];
    const float* Ur_b       = (const float*)d_in[10];
    const float* Wh         = (const float*)d_in[11];
    const float* Wh_b       = (const float*)d_in[12];
    const float* D1w        = (const float*)d_in[13];
    const float* D1b        = (const float*)d_in[14];
    const float* D2w        = (const float*)d_in[15];
    const float* D2b        = (const float*)d_in[16];
    const float* D3w        = (const float*)d_in[17];
    const float* D3b        = (const float*)d_in[18];
    float* out = (float*)d_out;

    float *x, *xz, *xr, *xh, *hA, *hB, *hrA, *hrB, *hUz, *sh, *zp, *sgr;
    float *rootr, *d1r, *d2;
    float *wxp, *wh2, *d2w, *wuz, *d1w;
    cudaGetSymbolAddress((void**)&x,     g_x);
    cudaGetSymbolAddress((void**)&xz,    g_xz);
    cudaGetSymbolAddress((void**)&xr,    g_xr);
    cudaGetSymbolAddress((void**)&xh,    g_xh);
    cudaGetSymbolAddress((void**)&hA,    g_hA);
    cudaGetSymbolAddress((void**)&hB,    g_hB);
    cudaGetSymbolAddress((void**)&hrA,   g_hrA);
    cudaGetSymbolAddress((void**)&hrB,   g_hrB);
    cudaGetSymbolAddress((void**)&hUz,   g_hUz);
    cudaGetSymbolAddress((void**)&sh,    g_sh);
    cudaGetSymbolAddress((void**)&zp,    g_zp);
    cudaGetSymbolAddress((void**)&sgr,   g_sgr);
    cudaGetSymbolAddress((void**)&rootr, g_rootr);
    cudaGetSymbolAddress((void**)&d1r,   g_d1r);
    cudaGetSymbolAddress((void**)&d2,    g_d2);
    cudaGetSymbolAddress((void**)&wxp,   g_wxp);
    cudaGetSymbolAddress((void**)&wh2,   g_wh2);
    cudaGetSymbolAddress((void**)&d2w,   g_d2w);
    cudaGetSymbolAddress((void**)&wuz,   g_wuz);
    cudaGetSymbolAddress((void**)&d1w,   g_d1w);

    cudaFuncSetAttribute(gemm_p<0>, cudaFuncAttributeMaxDynamicSharedMemorySize, SMEM_G);
    cudaFuncSetAttribute(gemm_p<1>, cudaFuncAttributeMaxDynamicSharedMemorySize, SMEM_G);
    cudaFuncSetAttribute(gemm_p<2>, cudaFuncAttributeMaxDynamicSharedMemorySize, SMEM_G);
    cudaFuncSetAttribute(gemm_p<3>, cudaFuncAttributeMaxDynamicSharedMemorySize, SMEM_G);

    const int KC1 = SP / TBK;    // 29
    const int KC2 = SP2 / TBK;   // 58

    // weight prep (round + repack + permute)
    dim3 pgrid((XPN * SP + 255) / 256, 5);
    prep_w<<<pgrid, 256>>>(Wz, Wr, Ur, Wh, D1w, D2w, wxp, wh2, d2w, wuz, d1w);

    // x = tf32(emb[fnode[fmess]]) permuted
    x_gather<<<MPAD, 256>>>(emb, fnode, fmess, x);

    dim3 blk(256);
    dim3 gxp(XPN / TBN, MPAD / TBM);   // fused x-proj: 22 x 47
    dim3 gx(8, MPAD / TBM);            // N=464 GEMMs (8 x 47)
    dim3 gw(15, MPAD / TBM);           // wide GEMM, N=960 (15 x 47)

    // Fused loop-invariant x-projections: [xz | xr | xh] = x @ [Wz1|Wr|Wh1]^T
    // (EPI=3: bias=Wz_b, exz param carries Ur_b, exh carries Wh_b)
    gemm_p<3><<<gxp, blk, SMEM_G>>>(x, SP, wxp, SP, Wz_b, xz, xr, xh, SP, KC1,
                                    Ur_b, Wh_b, nullptr, nullptr);

    // Step 1 specialized for h0 = 0
    init_h<<<MPAD, 256>>>(xz, xh, hA, hrA);

    float* hcur = hA;   float* hcurR = hrA;
    float* hnxt = hB;   float* hnxtR = hrB;
    for (int it = 0; it < NDEPTH - 1; ++it) {
        // wide: [hU | hz] = h @ [Ur | Wz2]^T  (N = 960)
        gemm_p<0><<<gw, blk, SMEM_G>>>(hcurR, SP, wuz, SP, nullptr, hUz, nullptr,
                                       nullptr, WNW, KC1, 0, 0, 0, 0);
        // sh, zp, sg in one pass
        gather_k<<<MPAD, 128>>>(hcur, hUz, xr, mess_graph, sh, zp, sgr);
        // h_new = GRU(sg @ Wh2^T) fused epilogue -> h natural + rounded permuted
        gemm_p<2><<<gx, blk, SMEM_G>>>(sgr, SP, wh2, SP, nullptr, hnxt, hnxtR,
                                       nullptr, SP, KC1, xz, xh, sh, zp);
        float* t = hcur; hcur = hnxt; hnxt = t;
        float* tr = hcurR; hcurR = hnxtR; hnxtR = tr;
    }

    // Root vectors + discriminator MLP
    root_k<<<NB, 256>>>(emb, fnode, root_idx, node_graph, hcur, rootr);

    dim3 gd(8, NB / TBM);   // (8, 2)
    gemm_p<1><<<gd, blk, SMEM_G>>>(rootr, SP2, d1w, SP2, D1b, nullptr, d1r,
                                   nullptr, SP, KC2, 0, 0, 0, 0);
    gemm_p<1><<<gd, blk, SMEM_G>>>(d1r, SP, d2w, SP, D2b, d2, nullptr,
                                   nullptr, SP, KC1, 0, 0, 0, 0);
    d3_k<<<NB, 128>>>(d2, D3w, D3b, out);
}